// round 8
// baseline (speedup 1.0000x reference)
#include <cuda_runtime.h>
#include <math.h>

// Problem constants
#define T_   2048
#define H_   2048
#define E_   8
#define I_   1408
#define I2_  2816
#define IS_  5632
#define NTOK 4
#define NTHR 512

// dynamic smem layout (floats)
//  xs   [NTOK][H_]     : 4*2048          = 8192 f  (32 KB)
//  prod [NTOK][IS_]    : 4*5632          = 22528 f (88 KB)
//  hs   [I_]           : 1408 f          (5.5 KB)
#define SM_XS   0
#define SM_PROD (SM_XS + NTOK * H_)
#define SM_HS   (SM_PROD + NTOK * IS_)
#define SM_FLOATS (SM_HS + I_)

__device__ __forceinline__ float warp_red(float s) {
    #pragma unroll
    for (int o = 16; o > 0; o >>= 1) s += __shfl_xor_sync(0xffffffffu, s, o);
    return s;
}

__global__ void __launch_bounds__(NTHR, 1)
k_moe(const float* __restrict__ x,
      const float* __restrict__ rw,    // [H, E]
      const float* __restrict__ guw,   // [E, H, 2I]
      const float* __restrict__ ow,    // [E, I, H]
      const float* __restrict__ sgw,   // [H, IS]
      const float* __restrict__ siw,   // [H, IS]
      const float* __restrict__ sow,   // [IS, H]
      const float* __restrict__ sgsw,  // [H, 1]
      float* __restrict__ out,         // [T, H]
      float* __restrict__ logits)      // [T, E] or null
{
    extern __shared__ float sm[];
    float* xs    = sm + SM_XS;     // [NTOK][H_]
    float* prods = sm + SM_PROD;   // [NTOK][IS_]
    float* hs    = sm + SM_HS;     // [I_]

    __shared__ float s_lg[NTOK][E_];
    __shared__ float s_sgdot[NTOK];
    __shared__ float s_w[NTOK][2];
    __shared__ float s_sig[NTOK];
    __shared__ int   s_eid[NTOK][2];

    const int tid  = threadIdx.x;
    const int wid  = tid >> 5;
    const int lane = tid & 31;
    const int t0   = blockIdx.x * NTOK;

    // ---- load x tile (coalesced: tokens are contiguous rows) ----
    for (int idx = tid; idx < NTOK * H_; idx += NTHR)
        xs[idx] = x[(size_t)t0 * H_ + idx];
    __syncthreads();

    // ---- router: warp w -> token (w>>2), experts {2*(w&3), 2*(w&3)+1} ----
    {
        int j  = wid >> 2;
        int e0 = (wid & 3) * 2;
        float s0 = 0.f, s1 = 0.f, sg = 0.f;
        const float* xj = xs + j * H_;
        for (int k = lane; k < H_; k += 32) {
            float xv = xj[k];
            s0 += xv * rw[(size_t)k * E_ + e0];
            s1 += xv * rw[(size_t)k * E_ + e0 + 1];
            if ((wid & 3) == 0) sg += xv * sgsw[k];
        }
        s0 = warp_red(s0); s1 = warp_red(s1);
        if ((wid & 3) == 0) sg = warp_red(sg);
        if (lane == 0) {
            s_lg[j][e0] = s0; s_lg[j][e0 + 1] = s1;
            if ((wid & 3) == 0) s_sgdot[j] = sg;
        }
    }
    __syncthreads();
    if (tid < NTOK) {
        int j = tid;
        if (logits) {
            #pragma unroll
            for (int e = 0; e < E_; e++) logits[(size_t)(t0 + j) * E_ + e] = s_lg[j][e];
        }
        int i0 = 0; float l0 = s_lg[j][0];
        #pragma unroll
        for (int e = 1; e < E_; e++) if (s_lg[j][e] > l0) { l0 = s_lg[j][e]; i0 = e; }
        int i1 = -1; float l1 = -3.4e38f;
        #pragma unroll
        for (int e = 0; e < E_; e++) if (e != i0 && s_lg[j][e] > l1) { l1 = s_lg[j][e]; i1 = e; }
        float r  = expf(l1 - l0);          // p1/p0
        float w0 = 1.f / (1.f + r);        // normalized top-2
        s_w[j][0] = w0; s_w[j][1] = 1.f - w0;
        s_eid[j][0] = i0; s_eid[j][1] = i1;
        s_sig[j] = 1.f / (1.f + expf(-s_sgdot[j]));
    }
    __syncthreads();

    // per-thread output accumulators: oacc[token][hb], h = hb*512 + tid
    float oacc[NTOK][4] = {};

    // ---- expert path: token-serial, expert-serial ----
    for (int j = 0; j < NTOK; j++) {
        const float* xj = xs + j * H_;
        #pragma unroll
        for (int ke = 0; ke < 2; ke++) {
            int e = s_eid[j][ke];
            float wk = s_w[j][ke];
            const float* We = guw + (size_t)e * H_ * I2_;

            // gate/up GEMV: thread owns m = mb*512+tid (mb 0..2; mb==2 only tid<384)
            float ag[3] = {}, au[3] = {};
            for (int k = 0; k < H_; k++) {
                float xv = xj[k];
                const float* row = We + (size_t)k * I2_;
                #pragma unroll
                for (int mb = 0; mb < 3; mb++) {
                    int m = mb * NTHR + tid;
                    if (mb < 2 || m < I_) {
                        ag[mb] += xv * row[m];
                        au[mb] += xv * row[m + I_];
                    }
                }
            }
            __syncthreads();   // hs free (previous down finished)
            #pragma unroll
            for (int mb = 0; mb < 3; mb++) {
                int m = mb * NTHR + tid;
                if (mb < 2 || m < I_) {
                    float g = ag[mb];
                    hs[m] = wk * au[mb] * g / (1.f + __expf(-g));
                }
            }
            __syncthreads();

            // down: oacc[j][hb] += sum_i hs[i] * Wo[e][i][h]
            const float* Wo = ow + (size_t)e * I_ * H_;
            for (int i = 0; i < I_; i++) {
                float hv = hs[i];
                const float* row = Wo + (size_t)i * H_;
                #pragma unroll
                for (int hb = 0; hb < 4; hb++)
                    oacc[j][hb] += hv * row[hb * NTHR + tid];
            }
            __syncthreads();
        }
    }

    // ---- shared expert: gate/inter with token-pair register blocking ----
    for (int jp = 0; jp < NTOK; jp += 2) {
        const float* x0 = xs + jp * H_;
        const float* x1 = xs + (jp + 1) * H_;
        float ag[2][11] = {}, au[2][11] = {};
        for (int k = 0; k < H_; k++) {
            float xv0 = x0[k], xv1 = x1[k];
            const float* rg = sgw + (size_t)k * IS_;
            const float* ri = siw + (size_t)k * IS_;
            #pragma unroll
            for (int ib = 0; ib < 11; ib++) {
                int i = ib * NTHR + tid;
                float wg = rg[i];
                float wi = ri[i];
                ag[0][ib] += xv0 * wg; ag[1][ib] += xv1 * wg;
                au[0][ib] += xv0 * wi; au[1][ib] += xv1 * wi;
            }
        }
        #pragma unroll
        for (int ib = 0; ib < 11; ib++) {
            int i = ib * NTHR + tid;
            #pragma unroll
            for (int jj = 0; jj < 2; jj++) {
                float g = ag[jj][ib];
                prods[(jp + jj) * IS_ + i] =
                    s_sig[jp + jj] * au[jj][ib] * g / (1.f + __expf(-g));
            }
        }
    }
    __syncthreads();

    // ---- shared down: amortize weight load over 4 tokens ----
    for (int i = 0; i < IS_; i++) {
        const float* row = sow + (size_t)i * H_;
        float p0 = prods[0 * IS_ + i];
        float p1 = prods[1 * IS_ + i];
        float p2 = prods[2 * IS_ + i];
        float p3 = prods[3 * IS_ + i];
        #pragma unroll
        for (int hb = 0; hb < 4; hb++) {
            float w = row[hb * NTHR + tid];
            oacc[0][hb] += p0 * w;
            oacc[1][hb] += p1 * w;
            oacc[2][hb] += p2 * w;
            oacc[3][hb] += p3 * w;
        }
    }

    // ---- write output (sole writer) ----
    #pragma unroll
    for (int j = 0; j < NTOK; j++)
        #pragma unroll
        for (int hb = 0; hb < 4; hb++)
            out[(size_t)(t0 + j) * H_ + hb * NTHR + tid] = oacc[j][hb];
}

// ---------------- launch ----------------
extern "C" void kernel_launch(void* const* d_in, const int* in_sizes, int n_in,
                              void* d_out, int out_size)
{
    // elements-vs-bytes detection
    int div = 1;
    {
        bool has_elem = false, has_byte = false;
        for (int i = 0; i < n_in; i++) {
            if (in_sizes[i] == 4194304)  has_elem = true;
            if (in_sizes[i] == 16777216) has_byte = true;
        }
        if (!has_elem && has_byte) div = 4;
    }

    const float *x = 0, *rw = 0, *guw = 0, *ow = 0, *sgsw = 0;
    const float* trio[3] = {0, 0, 0};
    int ntrio = 0;
    for (int i = 0; i < n_in; i++) {
        const float* p = (const float*)d_in[i];
        switch (in_sizes[i] / div) {
            case 4194304:  x    = p; break;   // hidden_states [2,1024,2048]
            case 16384:    rw   = p; break;   // router_w      [2048,8]
            case 46137344: guw  = p; break;   // gate_up_w     [8,2048,2816]
            case 23068672: ow   = p; break;   // out_w         [8,1408,2048]
            case 2048:     sgsw = p; break;   // scalar gate   [2048,1]
            case 11534336: if (ntrio < 3) trio[ntrio++] = p; break;
            default: break;
        }
    }
    const float* sgw = trio[0];   // gate, inter, out keep relative order
    const float* siw = trio[1];
    const float* sow = trio[2];
    if (!x || !rw || !guw || !ow || !sgsw || !sgw || !siw || !sow) {
        x    = (const float*)d_in[0];
        rw   = (const float*)d_in[1];
        guw  = (const float*)d_in[2];
        ow   = (const float*)d_in[3];
        sgw  = (const float*)d_in[4];
        siw  = (const float*)d_in[5];
        sow  = (const float*)d_in[6];
        sgsw = (const float*)d_in[7];
    }

    float* out = (float*)d_out;
    float* logits = (out_size == T_ * H_ + T_ * E_ ||
                     out_size == 4 * (T_ * H_ + T_ * E_))
                  ? (out + (size_t)T_ * H_) : (float*)0;

    const size_t smem = SM_FLOATS * sizeof(float);   // ~128.5 KB
    static bool attr_done = false;
    if (!attr_done) {
        cudaFuncSetAttribute(k_moe, cudaFuncAttributeMaxDynamicSharedMemorySize,
                             (int)smem);
        attr_done = true;
    }

    k_moe<<<T_ / NTOK, NTHR, smem>>>(x, rw, guw, ow, sgw, siw, sow, sgsw,
                                     out, logits);
}

// round 14
// speedup vs baseline: 3.1376x; 3.1376x over previous
#include <cuda_runtime.h>
#include <math.h>

// Problem constants
#define T_   2048
#define H_   2048
#define E_   8
#define I_   1408
#define I2_  2816
#define IS_  5632
#define NA_  4096
#define NB   296      // 2 blocks per SM on 148 SMs (GB300 has 152; still resident)
#define NT   256

// ---------------- device-global scratch (~69MB) ------------------------------
__device__ __align__(16) float g_h   [(size_t)NA_ * I_];    // expert hidden
__device__ __align__(16) float g_prod[(size_t)T_ * IS_];    // shared prod (sigma-scaled)
__device__ float g_topw[NA_];
__device__ float g_sig[T_];
__device__ int   g_expi[NA_];
__device__ int   g_pos[E_];
__device__ int   g_list[E_ * T_];
__device__ unsigned g_barc = 0;
__device__ unsigned g_gen  = 0;

// ---------------- device-wide barrier (replay-safe) --------------------------
__device__ __forceinline__ void gbar() {
    __syncthreads();
    if (threadIdx.x == 0) {
        __threadfence();
        unsigned gen = atomicAdd(&g_gen, 0u);
        unsigned tk  = atomicInc(&g_barc, NB - 1);   // wraps to 0 at last arrival
        if (tk == NB - 1) {
            atomicAdd(&g_gen, 1u);
        } else {
            while (atomicAdd(&g_gen, 0u) == gen) __nanosleep(64);
        }
        __threadfence();
    }
    __syncthreads();
}

__device__ __forceinline__ float warp_red(float s) {
    #pragma unroll
    for (int o = 16; o > 0; o >>= 1) s += __shfl_xor_sync(0xffffffffu, s, o);
    return s;
}

// ---------------- 64x64x16 GEMM tile, 256 threads, 4x4/thread ----------------
// GATHER: row ids from list; A row = aid>>ASHIFT; C row = aid>>CSHIFT.
// DUAL: C = scale * (A@B2) * silu(A@B1);  else C = scale * (A@B1)
// ACC: 0=store, 1=atomicAdd, 2=(__ldcg read)+= store
template <bool GATHER, int ASHIFT, int CSHIFT, bool DUAL, int ACC>
__device__ void gemm_tile(float* sm,
                          const float* __restrict__ A, int lda,
                          const float* __restrict__ B1, const float* __restrict__ B2, int ldb,
                          float* __restrict__ C, int ldc,
                          const float* __restrict__ scale,
                          const int* __restrict__ list, int count, int Kdim,
                          int mt, int nt)
{
    float* As  = sm;            // [16][64]
    float* Bs1 = sm + 1024;     // [16][64]
    float* Bs2 = sm + 2048;     // [16][64]

    const int tid = threadIdx.x;
    const int ty = tid >> 4, tx = tid & 15;

    float acc1[4][4] = {};
    float acc2[4][4] = {};

    const int lr  = tid >> 2;
    const int lk4 = (tid & 3) << 2;
    const int grA = mt * 64 + lr;
    const bool a_ok = grA < count;
    const float* arow;
    if (GATHER) {
        int aid = a_ok ? list[grA] : 0;
        arow = A + (size_t)(aid >> ASHIFT) * lda;
    } else {
        arow = A + (size_t)(a_ok ? grA : 0) * lda;
    }

    const int bkr = tid >> 4;
    const int bc  = (tid & 15) << 2;
    const float* brow1 = B1 + (size_t)bkr * ldb + nt * 64 + bc;
    const float* brow2 = DUAL ? (B2 + (size_t)bkr * ldb + nt * 64 + bc) : brow1;

    for (int k0 = 0; k0 < Kdim; k0 += 16) {
        float4 av = a_ok ? *(const float4*)(arow + k0 + lk4) : make_float4(0.f,0.f,0.f,0.f);
        float4 b1 = *(const float4*)(brow1 + (size_t)k0 * ldb);
        As[(lk4 + 0) * 64 + lr] = av.x;
        As[(lk4 + 1) * 64 + lr] = av.y;
        As[(lk4 + 2) * 64 + lr] = av.z;
        As[(lk4 + 3) * 64 + lr] = av.w;
        *(float4*)&Bs1[bkr * 64 + bc] = b1;
        if (DUAL) {
            float4 b2 = *(const float4*)(brow2 + (size_t)k0 * ldb);
            *(float4*)&Bs2[bkr * 64 + bc] = b2;
        }
        __syncthreads();

        #pragma unroll
        for (int kk = 0; kk < 16; kk++) {
            float4 a = *(const float4*)&As [kk * 64 + (ty << 2)];
            float4 b = *(const float4*)&Bs1[kk * 64 + (tx << 2)];
            acc1[0][0] += a.x*b.x; acc1[0][1] += a.x*b.y; acc1[0][2] += a.x*b.z; acc1[0][3] += a.x*b.w;
            acc1[1][0] += a.y*b.x; acc1[1][1] += a.y*b.y; acc1[1][2] += a.y*b.z; acc1[1][3] += a.y*b.w;
            acc1[2][0] += a.z*b.x; acc1[2][1] += a.z*b.y; acc1[2][2] += a.z*b.z; acc1[2][3] += a.z*b.w;
            acc1[3][0] += a.w*b.x; acc1[3][1] += a.w*b.y; acc1[3][2] += a.w*b.z; acc1[3][3] += a.w*b.w;
            if (DUAL) {
                float4 c = *(const float4*)&Bs2[kk * 64 + (tx << 2)];
                acc2[0][0] += a.x*c.x; acc2[0][1] += a.x*c.y; acc2[0][2] += a.x*c.z; acc2[0][3] += a.x*c.w;
                acc2[1][0] += a.y*c.x; acc2[1][1] += a.y*c.y; acc2[1][2] += a.y*c.z; acc2[1][3] += a.y*c.w;
                acc2[2][0] += a.z*c.x; acc2[2][1] += a.z*c.y; acc2[2][2] += a.z*c.z; acc2[2][3] += a.z*c.w;
                acc2[3][0] += a.w*c.x; acc2[3][1] += a.w*c.y; acc2[3][2] += a.w*c.z; acc2[3][3] += a.w*c.w;
            }
        }
        __syncthreads();
    }

    #pragma unroll
    for (int i = 0; i < 4; i++) {
        int gr = mt * 64 + (ty << 2) + i;
        if (gr < count) {
            int aid = GATHER ? list[gr] : gr;
            int cr  = aid >> CSHIFT;
            float sc = scale ? scale[aid] : 1.f;
            float4 v;
            if (DUAL) {
                float g0 = acc1[i][0], g1 = acc1[i][1], g2 = acc1[i][2], g3 = acc1[i][3];
                v.x = sc * acc2[i][0] * g0 / (1.f + __expf(-g0));
                v.y = sc * acc2[i][1] * g1 / (1.f + __expf(-g1));
                v.z = sc * acc2[i][2] * g2 / (1.f + __expf(-g2));
                v.w = sc * acc2[i][3] * g3 / (1.f + __expf(-g3));
            } else {
                v = make_float4(sc*acc1[i][0], sc*acc1[i][1], sc*acc1[i][2], sc*acc1[i][3]);
            }
            float* cp = C + (size_t)cr * ldc + nt * 64 + (tx << 2);
            if (ACC == 0) {
                *(float4*)cp = v;
            } else if (ACC == 1) {
                atomicAdd(cp + 0, v.x);
                atomicAdd(cp + 1, v.y);
                atomicAdd(cp + 2, v.z);
                atomicAdd(cp + 3, v.w);
            } else {
                float4 old = __ldcg((const float4*)cp);   // bypass L1: see P2 atomics
                old.x += v.x; old.y += v.y; old.z += v.z; old.w += v.w;
                *(float4*)cp = old;
            }
        }
    }
}

// ---------------- the single fused kernel ------------------------------------
__global__ void __launch_bounds__(NT, 2)
k_moe(const float* __restrict__ x,    const float* __restrict__ rw,
      const float* __restrict__ guw,  const float* __restrict__ ow,
      const float* __restrict__ sgw,  const float* __restrict__ siw,
      const float* __restrict__ sow,  const float* __restrict__ sgsw,
      float* __restrict__ out, float* __restrict__ logits)
{
    __shared__ __align__(16) float pool[3072];
    __shared__ float lg[E_];
    __shared__ float sgv;

    const int tid = threadIdx.x, bid = blockIdx.x;
    const int wid = tid >> 5, lane = tid & 31;

    // ---- P0a: zero out, reset counters, router ----
    for (size_t i = (size_t)bid * NT + tid; i < (size_t)T_ * H_; i += (size_t)NB * NT)
        out[i] = 0.f;
    if (bid == 0 && tid < E_) g_pos[tid] = 0;

    float* xs = pool;
    for (int t = bid; t < T_; t += NB) {
        __syncthreads();
        for (int i = tid; i < H_; i += NT) xs[i] = x[(size_t)t * H_ + i];
        __syncthreads();
        {   // 8 warps -> 8 experts
            float s = 0.f;
            for (int i = lane; i < H_; i += 32) s += xs[i] * rw[(size_t)i * E_ + wid];
            s = warp_red(s);
            if (lane == 0) lg[wid] = s;
        }
        if (wid == 0) {
            float s = 0.f;
            for (int i = lane; i < H_; i += 32) s += xs[i] * sgsw[i];
            s = warp_red(s);
            if (lane == 0) sgv = s;
        }
        __syncthreads();
        if (tid == 0) {
            if (logits) {
                #pragma unroll
                for (int e = 0; e < E_; e++) logits[(size_t)t * E_ + e] = lg[e];
            }
            int i0 = 0; float l0 = lg[0];
            #pragma unroll
            for (int e = 1; e < E_; e++) if (lg[e] > l0) { l0 = lg[e]; i0 = e; }
            int i1 = -1; float l1 = -3.4e38f;
            #pragma unroll
            for (int e = 0; e < E_; e++) if (e != i0 && lg[e] > l1) { l1 = lg[e]; i1 = e; }
            float r  = expf(l1 - l0);
            float w0 = 1.f / (1.f + r);
            g_topw[2 * t + 0] = w0;
            g_topw[2 * t + 1] = 1.f - w0;
            g_expi[2 * t + 0] = i0;
            g_expi[2 * t + 1] = i1;
            g_sig[t] = 1.f / (1.f + expf(-sgv));
        }
    }
    gbar();

    // ---- P0b: group assignments by expert ----
    for (int a = bid * NT + tid; a < NA_; a += NB * NT) {
        int e = g_expi[a];
        int p = atomicAdd(&g_pos[e], 1);     // p < 2048 guaranteed (<=1 per token per expert)
        g_list[e * T_ + p] = a;
    }
    gbar();

    // ---- P1: expert gate_up (gathered, fused silu*up) + shared gate/inter ----
    {
        const int GU = E_ * 32 * 22;         // expert slots
        const int PR = 32 * 88;              // shared prod tiles
        for (int s = bid; s < GU + PR; s += NB) {
            if (s < GU) {
                int e = s / (32 * 22), r = s % (32 * 22), mt = r / 22, nt = r % 22;
                int cnt = g_pos[e];
                if (mt * 64 >= cnt) continue;
                const float* W = guw + (size_t)e * H_ * I2_;
                gemm_tile<true, 1, 0, true, 0>(pool, x, H_, W, W + I_, I2_,
                    g_h, I_, (const float*)0, g_list + e * T_, cnt, H_, mt, nt);
            } else {
                int r = s - GU, mt = r / 88, nt = r % 88;
                gemm_tile<false, 0, 0, true, 0>(pool, x, H_, sgw, siw, IS_,
                    g_prod, IS_, g_sig, (const int*)0, T_, H_, mt, nt);
            }
        }
    }
    gbar();

    // ---- P2: expert down -> atomicAdd into out (2 commutative adds/element) ----
    for (int s = bid; s < E_ * 32 * 32; s += NB) {
        int e = s / 1024, r = s % 1024, mt = r / 32, nt = r % 32;
        int cnt = g_pos[e];
        if (mt * 64 >= cnt) continue;
        gemm_tile<true, 0, 1, false, 1>(pool, g_h, I_, ow + (size_t)e * I_ * H_,
            (const float*)0, H_, out, H_, g_topw, g_list + e * T_, cnt, I_, mt, nt);
    }
    gbar();

    // ---- P3: shared down -> out += prod @ sow (single writer/element) ----
    for (int s = bid; s < 32 * 32; s += NB) {
        int mt = s / 32, nt = s % 32;
        gemm_tile<false, 0, 0, false, 2>(pool, g_prod, IS_, sow, (const float*)0, H_,
            out, H_, (const float*)0, (const int*)0, T_, IS_, mt, nt);
    }
}

// ---------------- launch ----------------
extern "C" void kernel_launch(void* const* d_in, const int* in_sizes, int n_in,
                              void* d_out, int out_size)
{
    int div = 1;
    {
        bool has_elem = false, has_byte = false;
        for (int i = 0; i < n_in; i++) {
            if (in_sizes[i] == 4194304)  has_elem = true;
            if (in_sizes[i] == 16777216) has_byte = true;
        }
        if (!has_elem && has_byte) div = 4;
    }

    const float *x = 0, *rw = 0, *guw = 0, *ow = 0, *sgsw = 0;
    const float* trio[3] = {0, 0, 0};
    int ntrio = 0;
    for (int i = 0; i < n_in; i++) {
        const float* p = (const float*)d_in[i];
        switch (in_sizes[i] / div) {
            case 4194304:  x    = p; break;
            case 16384:    rw   = p; break;
            case 46137344: guw  = p; break;
            case 23068672: ow   = p; break;
            case 2048:     sgsw = p; break;
            case 11534336: if (ntrio < 3) trio[ntrio++] = p; break;
            default: break;
        }
    }
    const float* sgw = trio[0];
    const float* siw = trio[1];
    const float* sow = trio[2];
    if (!x || !rw || !guw || !ow || !sgsw || !sgw || !siw || !sow) {
        x    = (const float*)d_in[0];
        rw   = (const float*)d_in[1];
        guw  = (const float*)d_in[2];
        ow   = (const float*)d_in[3];
        sgw  = (const float*)d_in[4];
        siw  = (const float*)d_in[5];
        sow  = (const float*)d_in[6];
        sgsw = (const float*)d_in[7];
    }

    float* out = (float*)d_out;
    float* logits = (out_size == T_ * H_ + T_ * E_ ||
                     out_size == 4 * (T_ * H_ + T_ * E_))
                  ? (out + (size_t)T_ * H_) : (float*)0;

    k_moe<<<NB, NT>>>(x, rw, guw, ow, sgw, siw, sow, sgsw, out, logits);
}

// round 15
// speedup vs baseline: 7.1758x; 2.2871x over previous
#include <cuda_runtime.h>
#include <math.h>

// Problem constants
#define T_   2048
#define H_   2048
#define E_   8
#define I_   1408
#define I2_  2816
#define IS_  5632
#define NA_  4096
#define NB   296      // 2 blocks per SM on 148 SMs
#define NT   256
#define LDP  68       // padded smem row stride (floats): conflict-free frag loads

// ---------------- device-global scratch (~69MB) ------------------------------
__device__ __align__(16) float g_h   [(size_t)NA_ * I_];    // expert hidden
__device__ __align__(16) float g_prod[(size_t)T_ * IS_];    // shared prod (sigma-scaled)
__device__ float g_topw[NA_];
__device__ float g_sig[T_];
__device__ int   g_expi[NA_];
__device__ int   g_pos[E_];
__device__ int   g_list[E_ * T_];
__device__ unsigned g_barc = 0;
__device__ unsigned g_gen  = 0;

// ---------------- device-wide barrier (replay-safe) --------------------------
__device__ __forceinline__ void gbar() {
    __syncthreads();
    if (threadIdx.x == 0) {
        __threadfence();
        unsigned gen = atomicAdd(&g_gen, 0u);
        unsigned tk  = atomicInc(&g_barc, NB - 1);
        if (tk == NB - 1) {
            atomicAdd(&g_gen, 1u);
        } else {
            while (atomicAdd(&g_gen, 0u) == gen) __nanosleep(64);
        }
        __threadfence();
    }
    __syncthreads();
}

__device__ __forceinline__ float warp_red(float s) {
    #pragma unroll
    for (int o = 16; o > 0; o >>= 1) s += __shfl_xor_sync(0xffffffffu, s, o);
    return s;
}

__device__ __forceinline__ float f2tf(float f) {
    unsigned r;
    asm("cvt.rna.tf32.f32 %0, %1;" : "=r"(r) : "f"(f));
    return __uint_as_float(r);
}

__device__ __forceinline__ void mma_tf32(float c[4],
    unsigned a0, unsigned a1, unsigned a2, unsigned a3,
    unsigned b0, unsigned b1)
{
    asm volatile(
        "mma.sync.aligned.m16n8k8.row.col.f32.tf32.tf32.f32 "
        "{%0,%1,%2,%3},{%4,%5,%6,%7},{%8,%9},{%0,%1,%2,%3};"
        : "+f"(c[0]), "+f"(c[1]), "+f"(c[2]), "+f"(c[3])
        : "r"(a0), "r"(a1), "r"(a2), "r"(a3), "r"(b0), "r"(b1));
}

// ---------------- 64x64x16 GEMM tile, tf32 mma.sync, 8 warps -----------------
// Warps: wm = wid&3 (M, 16 rows each), wn = wid>>2 (N, 32 cols each; 4 n8 frags)
// GATHER: row ids from list; A row = aid>>ASHIFT; C row = aid>>CSHIFT.
// DUAL: C = scale * (A@B2) * silu(A@B1);  else C = scale * (A@B1)
// ACC: 0=store, 1=atomicAdd, 2=(__ldcg read)+= store
template <bool GATHER, int ASHIFT, int CSHIFT, bool DUAL, int ACC>
__device__ void gemm_tile(float* sm,
                          const float* __restrict__ A, int lda,
                          const float* __restrict__ B1, const float* __restrict__ B2, int ldb,
                          float* __restrict__ C, int ldc,
                          const float* __restrict__ scale,
                          const int* __restrict__ list, int count, int Kdim,
                          int mt, int nt)
{
    float* As  = sm;                 // [16][LDP]
    float* Bs1 = sm + 16 * LDP;      // [16][LDP]
    float* Bs2 = sm + 32 * LDP;      // [16][LDP]

    const int tid  = threadIdx.x;
    const int wid  = tid >> 5;
    const int lane = tid & 31;
    const int wm   = (wid & 3) * 16;
    const int wn   = (wid >> 2) * 32;
    const int mr   = lane >> 2;      // 0..7
    const int kr   = lane & 3;       // 0..3

    float acc1[4][4] = {};
    float acc2[4][4] = {};

    // A global load mapping (unchanged from fp32 version)
    const int lr  = tid >> 2;
    const int lk4 = (tid & 3) << 2;
    const int grA = mt * 64 + lr;
    const bool a_ok = grA < count;
    const float* arow;
    if (GATHER) {
        int aid = a_ok ? list[grA] : 0;
        arow = A + (size_t)(aid >> ASHIFT) * lda;
    } else {
        arow = A + (size_t)(a_ok ? grA : 0) * lda;
    }

    const int bkr = tid >> 4;
    const int bc  = (tid & 15) << 2;
    const float* brow1 = B1 + (size_t)bkr * ldb + nt * 64 + bc;
    const float* brow2 = DUAL ? (B2 + (size_t)bkr * ldb + nt * 64 + bc) : brow1;

    for (int k0 = 0; k0 < Kdim; k0 += 16) {
        float4 av = a_ok ? *(const float4*)(arow + k0 + lk4) : make_float4(0.f,0.f,0.f,0.f);
        float4 b1 = *(const float4*)(brow1 + (size_t)k0 * ldb);
        As[(lk4 + 0) * LDP + lr] = f2tf(av.x);
        As[(lk4 + 1) * LDP + lr] = f2tf(av.y);
        As[(lk4 + 2) * LDP + lr] = f2tf(av.z);
        As[(lk4 + 3) * LDP + lr] = f2tf(av.w);
        {
            float4 t = make_float4(f2tf(b1.x), f2tf(b1.y), f2tf(b1.z), f2tf(b1.w));
            *(float4*)&Bs1[bkr * LDP + bc] = t;
        }
        if (DUAL) {
            float4 b2 = *(const float4*)(brow2 + (size_t)k0 * ldb);
            float4 t = make_float4(f2tf(b2.x), f2tf(b2.y), f2tf(b2.z), f2tf(b2.w));
            *(float4*)&Bs2[bkr * LDP + bc] = t;
        }
        __syncthreads();

        #pragma unroll
        for (int ks = 0; ks < 2; ks++) {
            const int kb = ks * 8;
            unsigned a0 = __float_as_uint(As[(kb + kr) * LDP + wm + mr]);
            unsigned a1 = __float_as_uint(As[(kb + kr) * LDP + wm + mr + 8]);
            unsigned a2 = __float_as_uint(As[(kb + kr + 4) * LDP + wm + mr]);
            unsigned a3 = __float_as_uint(As[(kb + kr + 4) * LDP + wm + mr + 8]);
            #pragma unroll
            for (int f = 0; f < 4; f++) {
                const int nb = wn + f * 8;
                unsigned b0 = __float_as_uint(Bs1[(kb + kr) * LDP + nb + mr]);
                unsigned b1r = __float_as_uint(Bs1[(kb + kr + 4) * LDP + nb + mr]);
                mma_tf32(acc1[f], a0, a1, a2, a3, b0, b1r);
                if (DUAL) {
                    unsigned c0 = __float_as_uint(Bs2[(kb + kr) * LDP + nb + mr]);
                    unsigned c1 = __float_as_uint(Bs2[(kb + kr + 4) * LDP + nb + mr]);
                    mma_tf32(acc2[f], a0, a1, a2, a3, c0, c1);
                }
            }
        }
        __syncthreads();
    }

    // epilogue: thread holds rows {wm+mr, wm+mr+8}, cols wn + f*8 + 2*kr + {0,1}
    #pragma unroll
    for (int half = 0; half < 2; half++) {
        int gr = mt * 64 + wm + mr + half * 8;
        if (gr < count) {
            int aid = GATHER ? list[gr] : gr;
            int cr  = aid >> CSHIFT;
            float sc = scale ? scale[aid] : 1.f;
            float* crow = C + (size_t)cr * ldc + nt * 64 + wn;
            #pragma unroll
            for (int f = 0; f < 4; f++) {
                int ci = f * 8 + 2 * kr;
                float p0 = acc1[f][half * 2 + 0];
                float p1 = acc1[f][half * 2 + 1];
                float v0, v1;
                if (DUAL) {
                    v0 = sc * acc2[f][half * 2 + 0] * p0 / (1.f + __expf(-p0));
                    v1 = sc * acc2[f][half * 2 + 1] * p1 / (1.f + __expf(-p1));
                } else {
                    v0 = sc * p0;
                    v1 = sc * p1;
                }
                if (ACC == 0) {
                    *(float2*)(crow + ci) = make_float2(v0, v1);
                } else if (ACC == 1) {
                    atomicAdd(crow + ci + 0, v0);
                    atomicAdd(crow + ci + 1, v1);
                } else {
                    float2 old = __ldcg((const float2*)(crow + ci));
                    old.x += v0; old.y += v1;
                    *(float2*)(crow + ci) = old;
                }
            }
        }
    }
}

// ---------------- the single fused kernel ------------------------------------
__global__ void __launch_bounds__(NT, 2)
k_moe(const float* __restrict__ x,    const float* __restrict__ rw,
      const float* __restrict__ guw,  const float* __restrict__ ow,
      const float* __restrict__ sgw,  const float* __restrict__ siw,
      const float* __restrict__ sow,  const float* __restrict__ sgsw,
      float* __restrict__ out, float* __restrict__ logits)
{
    __shared__ __align__(16) float pool[48 * LDP];   // 3 tiles of [16][LDP]
    __shared__ float lg[E_];
    __shared__ float sgv;

    const int tid = threadIdx.x, bid = blockIdx.x;
    const int wid = tid >> 5, lane = tid & 31;

    // ---- P0a: zero out, reset counters, router ----
    for (size_t i = (size_t)bid * NT + tid; i < (size_t)T_ * H_; i += (size_t)NB * NT)
        out[i] = 0.f;
    if (bid == 0 && tid < E_) g_pos[tid] = 0;

    float* xs = pool;
    for (int t = bid; t < T_; t += NB) {
        __syncthreads();
        for (int i = tid; i < H_; i += NT) xs[i] = x[(size_t)t * H_ + i];
        __syncthreads();
        {   // 8 warps -> 8 experts
            float s = 0.f;
            for (int i = lane; i < H_; i += 32) s += xs[i] * rw[(size_t)i * E_ + wid];
            s = warp_red(s);
            if (lane == 0) lg[wid] = s;
        }
        if (wid == 0) {
            float s = 0.f;
            for (int i = lane; i < H_; i += 32) s += xs[i] * sgsw[i];
            s = warp_red(s);
            if (lane == 0) sgv = s;
        }
        __syncthreads();
        if (tid == 0) {
            if (logits) {
                #pragma unroll
                for (int e = 0; e < E_; e++) logits[(size_t)t * E_ + e] = lg[e];
            }
            int i0 = 0; float l0 = lg[0];
            #pragma unroll
            for (int e = 1; e < E_; e++) if (lg[e] > l0) { l0 = lg[e]; i0 = e; }
            int i1 = -1; float l1 = -3.4e38f;
            #pragma unroll
            for (int e = 0; e < E_; e++) if (e != i0 && lg[e] > l1) { l1 = lg[e]; i1 = e; }
            float r  = expf(l1 - l0);
            float w0 = 1.f / (1.f + r);
            g_topw[2 * t + 0] = w0;
            g_topw[2 * t + 1] = 1.f - w0;
            g_expi[2 * t + 0] = i0;
            g_expi[2 * t + 1] = i1;
            g_sig[t] = 1.f / (1.f + expf(-sgv));
        }
    }
    gbar();

    // ---- P0b: group assignments by expert ----
    for (int a = bid * NT + tid; a < NA_; a += NB * NT) {
        int e = g_expi[a];
        int p = atomicAdd(&g_pos[e], 1);
        g_list[e * T_ + p] = a;
    }
    gbar();

    // ---- P1: expert gate_up (gathered, fused silu*up) + shared gate/inter ----
    {
        const int GU = E_ * 32 * 22;
        const int PR = 32 * 88;
        for (int s = bid; s < GU + PR; s += NB) {
            if (s < GU) {
                int e = s / (32 * 22), r = s % (32 * 22), mt = r / 22, nt = r % 22;
                int cnt = g_pos[e];
                if (mt * 64 >= cnt) continue;
                const float* W = guw + (size_t)e * H_ * I2_;
                gemm_tile<true, 1, 0, true, 0>(pool, x, H_, W, W + I_, I2_,
                    g_h, I_, (const float*)0, g_list + e * T_, cnt, H_, mt, nt);
            } else {
                int r = s - GU, mt = r / 88, nt = r % 88;
                gemm_tile<false, 0, 0, true, 0>(pool, x, H_, sgw, siw, IS_,
                    g_prod, IS_, g_sig, (const int*)0, T_, H_, mt, nt);
            }
        }
    }
    gbar();

    // ---- P2: expert down -> atomicAdd into out (2 commutative adds/element) ----
    for (int s = bid; s < E_ * 32 * 32; s += NB) {
        int e = s / 1024, r = s % 1024, mt = r / 32, nt = r % 32;
        int cnt = g_pos[e];
        if (mt * 64 >= cnt) continue;
        gemm_tile<true, 0, 1, false, 1>(pool, g_h, I_, ow + (size_t)e * I_ * H_,
            (const float*)0, H_, out, H_, g_topw, g_list + e * T_, cnt, I_, mt, nt);
    }
    gbar();

    // ---- P3: shared down -> out += prod @ sow (single writer/element) ----
    for (int s = bid; s < 32 * 32; s += NB) {
        int mt = s / 32, nt = s % 32;
        gemm_tile<false, 0, 0, false, 2>(pool, g_prod, IS_, sow, (const float*)0, H_,
            out, H_, (const float*)0, (const int*)0, T_, IS_, mt, nt);
    }
}

// ---------------- launch ----------------
extern "C" void kernel_launch(void* const* d_in, const int* in_sizes, int n_in,
                              void* d_out, int out_size)
{
    int div = 1;
    {
        bool has_elem = false, has_byte = false;
        for (int i = 0; i < n_in; i++) {
            if (in_sizes[i] == 4194304)  has_elem = true;
            if (in_sizes[i] == 16777216) has_byte = true;
        }
        if (!has_elem && has_byte) div = 4;
    }

    const float *x = 0, *rw = 0, *guw = 0, *ow = 0, *sgsw = 0;
    const float* trio[3] = {0, 0, 0};
    int ntrio = 0;
    for (int i = 0; i < n_in; i++) {
        const float* p = (const float*)d_in[i];
        switch (in_sizes[i] / div) {
            case 4194304:  x    = p; break;
            case 16384:    rw   = p; break;
            case 46137344: guw  = p; break;
            case 23068672: ow   = p; break;
            case 2048:     sgsw = p; break;
            case 11534336: if (ntrio < 3) trio[ntrio++] = p; break;
            default: break;
        }
    }
    const float* sgw = trio[0];
    const float* siw = trio[1];
    const float* sow = trio[2];
    if (!x || !rw || !guw || !ow || !sgsw || !sgw || !siw || !sow) {
        x    = (const float*)d_in[0];
        rw   = (const float*)d_in[1];
        guw  = (const float*)d_in[2];
        ow   = (const float*)d_in[3];
        sgw  = (const float*)d_in[4];
        siw  = (const float*)d_in[5];
        sow  = (const float*)d_in[6];
        sgsw = (const float*)d_in[7];
    }

    float* out = (float*)d_out;
    float* logits = (out_size == T_ * H_ + T_ * E_ ||
                     out_size == 4 * (T_ * H_ + T_ * E_))
                  ? (out + (size_t)T_ * H_) : (float*)0;

    k_moe<<<NB, NT>>>(x, rw, guw, ow, sgw, siw, sow, sgsw, out, logits);
}

// round 17
// speedup vs baseline: 12.9853x; 1.8096x over previous
#include <cuda_runtime.h>
#include <math.h>

// Problem constants
#define T_   2048
#define H_   2048
#define E_   8
#define I_   1408
#define I2_  2816
#define IS_  5632
#define NA_  4096
#define NB   296      // 2 blocks per SM on 148 SMs
#define NT   256

// smem geometry (floats): A[16][136] + B1[16][72] + B2[16][72] per buffer
#define LDA_S 136     // ≡8 mod 32 -> conflict-free frag reads
#define LDB_S 72      // ≡8 mod 32
#define ASZ  (16 * LDA_S)            // 2176
#define BSZ  (16 * LDB_S)            // 1152
#define BUFSZ (ASZ + 2 * BSZ)        // 4480
#define POOLSZ (2 * BUFSZ)           // 8960 floats = 35840 B

// ---------------- device-global scratch (~69MB) ------------------------------
__device__ __align__(16) float g_h   [(size_t)NA_ * I_];
__device__ __align__(16) float g_prod[(size_t)T_ * IS_];
__device__ float g_topw[NA_];
__device__ float g_sig[T_];
__device__ int   g_expi[NA_];
__device__ int   g_pos[E_];
__device__ int   g_list[E_ * T_];
__device__ unsigned g_barc = 0;
__device__ unsigned g_gen  = 0;

// ---------------- device-wide barrier (replay-safe) --------------------------
__device__ __forceinline__ void gbar() {
    __syncthreads();
    if (threadIdx.x == 0) {
        __threadfence();
        unsigned gen = atomicAdd(&g_gen, 0u);
        unsigned tk  = atomicInc(&g_barc, NB - 1);
        if (tk == NB - 1) {
            atomicAdd(&g_gen, 1u);
        } else {
            while (atomicAdd(&g_gen, 0u) == gen) __nanosleep(64);
        }
        __threadfence();
    }
    __syncthreads();
}

__device__ __forceinline__ float warp_red(float s) {
    #pragma unroll
    for (int o = 16; o > 0; o >>= 1) s += __shfl_xor_sync(0xffffffffu, s, o);
    return s;
}

__device__ __forceinline__ float f2tf(float f) {
    unsigned r;
    asm("cvt.rna.tf32.f32 %0, %1;" : "=r"(r) : "f"(f));
    return __uint_as_float(r);
}

__device__ __forceinline__ void mma_tf32(float c[4],
    unsigned a0, unsigned a1, unsigned a2, unsigned a3,
    unsigned b0, unsigned b1)
{
    asm volatile(
        "mma.sync.aligned.m16n8k8.row.col.f32.tf32.tf32.f32 "
        "{%0,%1,%2,%3},{%4,%5,%6,%7},{%8,%9},{%0,%1,%2,%3};"
        : "+f"(c[0]), "+f"(c[1]), "+f"(c[2]), "+f"(c[3])
        : "r"(a0), "r"(a1), "r"(a2), "r"(a3), "r"(b0), "r"(b1));
}

// ---------------- 128x64x16 GEMM tile, tf32 mma, warp tile m32n32 ------------
// 8 warps: wm=(wid&3)*32 (M), wn=(wid>>2)*32 (N). Double-buffered, 1 sync/k16.
// GATHER: row ids from list; A row = aid>>ASHIFT; C row = aid>>CSHIFT.
// DUAL: C = scale * (A@B2) * silu(A@B1);  else C = scale * (A@B1)
// ACC: 0=store, 1=atomicAdd, 2=(__ldcg read)+= store
template <bool GATHER, int ASHIFT, int CSHIFT, bool DUAL, int ACC>
__device__ void gemm_tile(float* sm,
                          const float* __restrict__ A, int lda,
                          const float* __restrict__ B1, const float* __restrict__ B2, int ldb,
                          float* __restrict__ C, int ldc,
                          const float* __restrict__ scale,
                          const int* __restrict__ list, int count, int Kdim,
                          int mt, int nt)
{
    const int tid  = threadIdx.x;
    const int wid  = tid >> 5;
    const int lane = tid & 31;
    const int wm   = (wid & 3) * 32;
    const int wn   = (wid >> 2) * 32;
    const int mr   = lane >> 2;      // 0..7
    const int kr   = lane & 3;       // 0..3

    float acc1[2][4][4] = {};
    float acc2[2][4][4] = {};

    // A fill: thread -> (row, 8-wide k half)
    const int frow = tid >> 1;            // 0..127
    const int fkh  = (tid & 1) * 8;       // 0 or 8
    const int grA  = mt * 128 + frow;
    const bool a_ok = grA < count;
    const float* arow;
    if (GATHER) {
        int aid = a_ok ? list[grA] : 0;
        arow = A + (size_t)(aid >> ASHIFT) * lda;
    } else {
        arow = A + (size_t)(a_ok ? grA : 0) * lda;
    }
    // B fill: thread -> (k row, 4-wide n)
    const int bkr = tid >> 4;             // 0..15
    const int bc  = (tid & 15) << 2;      // 0..60
    const float* brow1 = B1 + (size_t)bkr * ldb + nt * 64 + bc;
    const float* brow2 = DUAL ? (B2 + (size_t)bkr * ldb + nt * 64 + bc) : brow1;

    float4 a0v, a1v, bv, cv;
    auto loadG = [&](int k0) {
        if (a_ok) {
            a0v = *(const float4*)(arow + k0 + fkh);
            a1v = *(const float4*)(arow + k0 + fkh + 4);
        } else {
            a0v = make_float4(0.f,0.f,0.f,0.f);
            a1v = a0v;
        }
        bv = *(const float4*)(brow1 + (size_t)k0 * ldb);
        if (DUAL) cv = *(const float4*)(brow2 + (size_t)k0 * ldb);
    };
    auto storeS = [&](float* buf) {
        float* As  = buf;
        float* Bs1 = buf + ASZ;
        float* Bs2 = buf + ASZ + BSZ;
        As[(fkh + 0) * LDA_S + frow] = f2tf(a0v.x);
        As[(fkh + 1) * LDA_S + frow] = f2tf(a0v.y);
        As[(fkh + 2) * LDA_S + frow] = f2tf(a0v.z);
        As[(fkh + 3) * LDA_S + frow] = f2tf(a0v.w);
        As[(fkh + 4) * LDA_S + frow] = f2tf(a1v.x);
        As[(fkh + 5) * LDA_S + frow] = f2tf(a1v.y);
        As[(fkh + 6) * LDA_S + frow] = f2tf(a1v.z);
        As[(fkh + 7) * LDA_S + frow] = f2tf(a1v.w);
        *(float4*)&Bs1[bkr * LDB_S + bc] =
            make_float4(f2tf(bv.x), f2tf(bv.y), f2tf(bv.z), f2tf(bv.w));
        if (DUAL)
            *(float4*)&Bs2[bkr * LDB_S + bc] =
                make_float4(f2tf(cv.x), f2tf(cv.y), f2tf(cv.z), f2tf(cv.w));
    };
    auto compute = [&](const float* buf) {
        const float* As  = buf;
        const float* Bs1 = buf + ASZ;
        const float* Bs2 = buf + ASZ + BSZ;
        #pragma unroll
        for (int ks = 0; ks < 2; ks++) {
            const int kb = ks * 8;
            unsigned a[2][4];
            #pragma unroll
            for (int mf = 0; mf < 2; mf++) {
                int rb = wm + mf * 16 + mr;
                a[mf][0] = __float_as_uint(As[(kb + kr) * LDA_S + rb]);
                a[mf][1] = __float_as_uint(As[(kb + kr) * LDA_S + rb + 8]);
                a[mf][2] = __float_as_uint(As[(kb + kr + 4) * LDA_S + rb]);
                a[mf][3] = __float_as_uint(As[(kb + kr + 4) * LDA_S + rb + 8]);
            }
            #pragma unroll
            for (int f = 0; f < 4; f++) {
                int nb = wn + f * 8 + mr;
                unsigned b0 = __float_as_uint(Bs1[(kb + kr) * LDB_S + nb]);
                unsigned b1 = __float_as_uint(Bs1[(kb + kr + 4) * LDB_S + nb]);
                mma_tf32(acc1[0][f], a[0][0], a[0][1], a[0][2], a[0][3], b0, b1);
                mma_tf32(acc1[1][f], a[1][0], a[1][1], a[1][2], a[1][3], b0, b1);
                if (DUAL) {
                    unsigned c0 = __float_as_uint(Bs2[(kb + kr) * LDB_S + nb]);
                    unsigned c1 = __float_as_uint(Bs2[(kb + kr + 4) * LDB_S + nb]);
                    mma_tf32(acc2[0][f], a[0][0], a[0][1], a[0][2], a[0][3], c0, c1);
                    mma_tf32(acc2[1][f], a[1][0], a[1][1], a[1][2], a[1][3], c0, c1);
                }
            }
        }
    };

    const int nk = Kdim >> 4;
    loadG(0);
    storeS(sm);
    __syncthreads();
    for (int t = 0; t < nk; t++) {
        const float* cur = sm + (t & 1) * BUFSZ;
        if (t + 1 < nk) loadG((t + 1) * 16);
        compute(cur);
        if (t + 1 < nk) storeS(sm + ((t + 1) & 1) * BUFSZ);
        __syncthreads();
    }

    // epilogue: rows wm + mf*16 + mr + half*8; cols wn + f*8 + 2*kr + {0,1}
    #pragma unroll
    for (int mf = 0; mf < 2; mf++)
    #pragma unroll
    for (int half = 0; half < 2; half++) {
        int gr = mt * 128 + wm + mf * 16 + mr + half * 8;
        if (gr < count) {
            int aid = GATHER ? list[gr] : gr;
            int cr  = aid >> CSHIFT;
            float sc = scale ? scale[aid] : 1.f;
            float* crow = C + (size_t)cr * ldc + nt * 64 + wn;
            #pragma unroll
            for (int f = 0; f < 4; f++) {
                int ci = f * 8 + 2 * kr;
                float p0 = acc1[mf][f][half * 2 + 0];
                float p1 = acc1[mf][f][half * 2 + 1];
                float v0, v1;
                if (DUAL) {
                    v0 = sc * acc2[mf][f][half * 2 + 0] * p0 / (1.f + __expf(-p0));
                    v1 = sc * acc2[mf][f][half * 2 + 1] * p1 / (1.f + __expf(-p1));
                } else {
                    v0 = sc * p0;
                    v1 = sc * p1;
                }
                if (ACC == 0) {
                    *(float2*)(crow + ci) = make_float2(v0, v1);
                } else if (ACC == 1) {
                    atomicAdd(crow + ci + 0, v0);
                    atomicAdd(crow + ci + 1, v1);
                } else {
                    float2 old = __ldcg((const float2*)(crow + ci));
                    old.x += v0; old.y += v1;
                    *(float2*)(crow + ci) = old;
                }
            }
        }
    }
}

// ---------------- the single fused kernel ------------------------------------
__global__ void __launch_bounds__(NT, 2)
k_moe(const float* __restrict__ x,    const float* __restrict__ rw,
      const float* __restrict__ guw,  const float* __restrict__ ow,
      const float* __restrict__ sgw,  const float* __restrict__ siw,
      const float* __restrict__ sow,  const float* __restrict__ sgsw,
      float* __restrict__ out, float* __restrict__ logits)
{
    __shared__ __align__(16) float pool[POOLSZ];
    __shared__ float lg[E_];
    __shared__ float sgv;

    const int tid = threadIdx.x, bid = blockIdx.x;
    const int wid = tid >> 5, lane = tid & 31;

    // ---- P0a: zero out, reset counters, router ----
    for (size_t i = (size_t)bid * NT + tid; i < (size_t)T_ * H_; i += (size_t)NB * NT)
        out[i] = 0.f;
    if (bid == 0 && tid < E_) g_pos[tid] = 0;

    float* xs = pool;
    for (int t = bid; t < T_; t += NB) {
        __syncthreads();
        for (int i = tid; i < H_; i += NT) xs[i] = x[(size_t)t * H_ + i];
        __syncthreads();
        {
            float s = 0.f;
            for (int i = lane; i < H_; i += 32) s += xs[i] * rw[(size_t)i * E_ + wid];
            s = warp_red(s);
            if (lane == 0) lg[wid] = s;
        }
        if (wid == 0) {
            float s = 0.f;
            for (int i = lane; i < H_; i += 32) s += xs[i] * sgsw[i];
            s = warp_red(s);
            if (lane == 0) sgv = s;
        }
        __syncthreads();
        if (tid == 0) {
            if (logits) {
                #pragma unroll
                for (int e = 0; e < E_; e++) logits[(size_t)t * E_ + e] = lg[e];
            }
            int i0 = 0; float l0 = lg[0];
            #pragma unroll
            for (int e = 1; e < E_; e++) if (lg[e] > l0) { l0 = lg[e]; i0 = e; }
            int i1 = -1; float l1 = -3.4e38f;
            #pragma unroll
            for (int e = 0; e < E_; e++) if (e != i0 && lg[e] > l1) { l1 = lg[e]; i1 = e; }
            float r  = expf(l1 - l0);
            float w0 = 1.f / (1.f + r);
            g_topw[2 * t + 0] = w0;
            g_topw[2 * t + 1] = 1.f - w0;
            g_expi[2 * t + 0] = i0;
            g_expi[2 * t + 1] = i1;
            g_sig[t] = 1.f / (1.f + expf(-sgv));
        }
    }
    gbar();

    // ---- P0b: group assignments by expert ----
    for (int a = bid * NT + tid; a < NA_; a += NB * NT) {
        int e = g_expi[a];
        int p = atomicAdd(&g_pos[e], 1);
        g_list[e * T_ + p] = a;
    }
    gbar();

    // ---- P1: expert gate_up (gathered, fused silu*up) + shared gate/inter ----
    {
        const int GU = E_ * 16 * 22;     // M tiles 16 (2048/128), N tiles 22 (1408/64)
        const int PR = 16 * 88;          // shared: 16 x (5632/64)
        for (int s = bid; s < GU + PR; s += NB) {
            if (s < GU) {
                int e = s / (16 * 22), r = s % (16 * 22), mt = r / 22, nt = r % 22;
                int cnt = g_pos[e];
                if (mt * 128 >= cnt) continue;
                const float* W = guw + (size_t)e * H_ * I2_;
                gemm_tile<true, 1, 0, true, 0>(pool, x, H_, W, W + I_, I2_,
                    g_h, I_, (const float*)0, g_list + e * T_, cnt, H_, mt, nt);
            } else {
                int r = s - GU, mt = r / 88, nt = r % 88;
                gemm_tile<false, 0, 0, true, 0>(pool, x, H_, sgw, siw, IS_,
                    g_prod, IS_, g_sig, (const int*)0, T_, H_, mt, nt);
            }
        }
    }
    gbar();

    // ---- P2: expert down -> atomicAdd into out (2 commutative adds/element) ----
    for (int s = bid; s < E_ * 16 * 32; s += NB) {
        int e = s / (16 * 32), r = s % (16 * 32), mt = r / 32, nt = r % 32;
        int cnt = g_pos[e];
        if (mt * 128 >= cnt) continue;
        gemm_tile<true, 0, 1, false, 1>(pool, g_h, I_, ow + (size_t)e * I_ * H_,
            (const float*)0, H_, out, H_, g_topw, g_list + e * T_, cnt, I_, mt, nt);
    }
    gbar();

    // ---- P3: shared down -> out += prod @ sow (single writer/element) ----
    for (int s = bid; s < 16 * 32; s += NB) {
        int mt = s / 32, nt = s % 32;
        gemm_tile<false, 0, 0, false, 2>(pool, g_prod, IS_, sow, (const float*)0, H_,
            out, H_, (const float*)0, (const int*)0, T_, IS_, mt, nt);
    }
}

// ---------------- launch ----------------
extern "C" void kernel_launch(void* const* d_in, const int* in_sizes, int n_in,
                              void* d_out, int out_size)
{
    int div = 1;
    {
        bool has_elem = false, has_byte = false;
        for (int i = 0; i < n_in; i++) {
            if (in_sizes[i] == 4194304)  has_elem = true;
            if (in_sizes[i] == 16777216) has_byte = true;
        }
        if (!has_elem && has_byte) div = 4;
    }

    const float *x = 0, *rw = 0, *guw = 0, *ow = 0, *sgsw = 0;
    const float* trio[3] = {0, 0, 0};
    int ntrio = 0;
    for (int i = 0; i < n_in; i++) {
        const float* p = (const float*)d_in[i];
        switch (in_sizes[i] / div) {
            case 4194304:  x    = p; break;
            case 16384:    rw   = p; break;
            case 46137344: guw  = p; break;
            case 23068672: ow   = p; break;
            case 2048:     sgsw = p; break;
            case 11534336: if (ntrio < 3) trio[ntrio++] = p; break;
            default: break;
        }
    }
    const float* sgw = trio[0];
    const float* siw = trio[1];
    const float* sow = trio[2];
    if (!x || !rw || !guw || !ow || !sgsw || !sgw || !siw || !sow) {
        x    = (const float*)d_in[0];
        rw   = (const float*)d_in[1];
        guw  = (const float*)d_in[2];
        ow   = (const float*)d_in[3];
        sgw  = (const float*)d_in[4];
        siw  = (const float*)d_in[5];
        sow  = (const float*)d_in[6];
        sgsw = (const float*)d_in[7];
    }

    float* out = (float*)d_out;
    float* logits = (out_size == T_ * H_ + T_ * E_ ||
                     out_size == 4 * (T_ * H_ + T_ * E_))
                  ? (out + (size_t)T_ * H_) : (float*)0;

    k_moe<<<NB, NT>>>(x, rw, guw, ow, sgw, siw, sow, sgsw, out, logits);
}